// round 4
// baseline (speedup 1.0000x reference)
#include <cuda_runtime.h>

// Fixed problem shapes
#define P_FULL   65536    // H*W
#define PN       12544    // sampled points
#define M_TGT    80       // targets
#define M_HALF   40       // targets per CTA half
#define K_CLS    134      // classes
#define N_ROWS   400      // bs*Q
#define NT       256      // threads per main block
#define NGROUPS  (PN / 4)             // 3136 groups of 4 points
#define GPT      (NGROUPS / NT)       // 12 base groups/thread
#define GREM     (NGROUPS - GPT * NT) // 64 threads get one extra

typedef unsigned long long ull;

// Static scratch
__device__ unsigned g_patT[10 * NGROUPS]; // plane w: patterns for m=8w..8w+7, indexed by group
__device__ int g_ysum_i[M_TGT];           // sum_j y[m,j] (integer counts)

// ---------- f32x2 helpers ----------
__device__ __forceinline__ ull f2pack(float a, float b) {
    ull r; asm("mov.b64 %0, {%1, %2};" : "=l"(r) : "f"(a), "f"(b)); return r;
}
__device__ __forceinline__ ull add2(ull a, ull b) {
    ull r; asm("add.rn.f32x2 %0, %1, %2;" : "=l"(r) : "l"(a), "l"(b)); return r;
}

// spread 8 bits so bit k lands at position 4k
__device__ __forceinline__ unsigned expand8(unsigned v) {
    v = (v | (v << 12)) & 0x000F000Fu;
    v = (v | (v << 6))  & 0x03030303u;
    v = (v | (v << 3))  & 0x11111111u;
    return v;
}

// ---------------------------------------------------------------------------
// Zero kernel (ysum accumulators) — graph-safe, runs each replay.
// ---------------------------------------------------------------------------
__global__ void hm_zero_kernel() {
    if (threadIdx.x < M_TGT) g_ysum_i[threadIdx.x] = 0;
}

// ---------------------------------------------------------------------------
// Prep: one warp per block, one thread per sampled point. Builds per-point
// 80-bit target mask, accumulates ysum via ballot+RED, and interleaves each
// 4-point group's bits into nibble-pattern planes via shuffles.
// Grid: 392 blocks x 32 threads.
// ---------------------------------------------------------------------------
__global__ void hm_prep_kernel(const float* __restrict__ tgt_masks,
                               const int*   __restrict__ point_idx) {
    const int lane = threadIdx.x;
    const int j    = blockIdx.x * 32 + lane;
    const int pj   = __ldg(point_idx + j);

    unsigned w0 = 0u, w1 = 0u, w2 = 0u;
#pragma unroll
    for (int m = 0; m < 32; m++)
        if (__ldg(tgt_masks + (size_t)m * P_FULL + pj) != 0.0f) w0 |= (1u << m);
#pragma unroll
    for (int m = 0; m < 32; m++)
        if (__ldg(tgt_masks + (size_t)(32 + m) * P_FULL + pj) != 0.0f) w1 |= (1u << m);
#pragma unroll
    for (int m = 0; m < 16; m++)
        if (__ldg(tgt_masks + (size_t)(64 + m) * P_FULL + pj) != 0.0f) w2 |= (1u << m);

    // ysum via ballot + one RED per m
#pragma unroll
    for (int m = 0; m < M_TGT; m++) {
        unsigned bit;
        if (m < 32)      bit = (w0 >> m) & 1u;
        else if (m < 64) bit = (w1 >> (m - 32)) & 1u;
        else             bit = (w2 >> (m - 64)) & 1u;
        unsigned ball = __ballot_sync(0xffffffffu, bit != 0u);
        if (lane == 0) atomicAdd(&g_ysum_i[m], __popc(ball));
    }

    // nibble-pattern planes: word w of group g holds, at bits [4k,4k+4),
    // the 4-point pattern of target m = 8w+k.
    const int base = lane & ~3;        // group leader lane
    const int g    = j >> 2;
#pragma unroll
    for (int w = 0; w < 10; w++) {
        unsigned byte;
        if (w < 4)      byte = (w0 >> (8 * w)) & 0xFFu;
        else if (w < 8) byte = (w1 >> (8 * (w - 4))) & 0xFFu;
        else            byte = (w2 >> (8 * (w - 8))) & 0xFFu;
        unsigned e = expand8(byte);
        unsigned p = __shfl_sync(0xffffffffu, e, base)
                   | (__shfl_sync(0xffffffffu, e, base + 1) << 1)
                   | (__shfl_sync(0xffffffffu, e, base + 2) << 2)
                   | (__shfl_sync(0xffffffffu, e, base + 3) << 3);
        if ((lane & 3) == 0) g_patT[w * NGROUPS + g] = p;
    }
}

// ---------------------------------------------------------------------------
// Main kernel: grid 800 = (n, half). Each CTA handles 40 targets of one row n.
// Four-Russians: per 4-point group, build 16 subset sums of packed
// (x, sigmoid) f32x2 in a per-thread smem LUT; one LDS.64 + FADD2 per
// (group, target).
// ---------------------------------------------------------------------------
__global__ void __launch_bounds__(NT, 2)
hm_main_kernel(const float* __restrict__ pred_logits,
               const float* __restrict__ pred_masks,
               const int*   __restrict__ tgt_labels,
               const int*   __restrict__ point_idx,
               float*       __restrict__ out) {
    const int n    = blockIdx.x >> 1;
    const int h    = blockIdx.x & 1;          // target half: m in [40h, 40h+40)
    const int tid  = threadIdx.x;
    const int lane = tid & 31;
    const float* __restrict__ xrow = pred_masks + (size_t)n * P_FULL;
    const unsigned* __restrict__ pat = g_patT + (size_t)(5 * h) * NGROUPS;

    // Per-thread subset LUT: lut[nib*NT + tid] -> banks 2*tid (conflict-free)
    __shared__ ull lut[16 * NT];

    ull acc[M_HALF];
#pragma unroll
    for (int m = 0; m < M_HALF; m++) acc[m] = 0ull;
    float spsum = 0.0f, sgsum = 0.0f;

    const int niter = (tid < GREM) ? (GPT + 1) : GPT;

    // prefetch first group's gathers + patterns
    int4  pidx = __ldg((const int4*)point_idx + tid);
    float nx0 = __ldg(xrow + pidx.x);
    float nx1 = __ldg(xrow + pidx.y);
    float nx2 = __ldg(xrow + pidx.z);
    float nx3 = __ldg(xrow + pidx.w);
    unsigned npw0 = __ldg(pat + 0 * NGROUPS + tid);
    unsigned npw1 = __ldg(pat + 1 * NGROUPS + tid);
    unsigned npw2 = __ldg(pat + 2 * NGROUPS + tid);
    unsigned npw3 = __ldg(pat + 3 * NGROUPS + tid);
    unsigned npw4 = __ldg(pat + 4 * NGROUPS + tid);

#pragma unroll 1
    for (int i = 0; i < niter; i++) {
        const int g = tid + i * NT;
        float x0 = nx0, x1 = nx1, x2 = nx2, x3 = nx3;
        unsigned pw[5] = {npw0, npw1, npw2, npw3, npw4};
        if (i + 1 < niter) {
            int gn = g + NT;
            int4 np = __ldg((const int4*)point_idx + gn);
            nx0 = __ldg(xrow + np.x);
            nx1 = __ldg(xrow + np.y);
            nx2 = __ldg(xrow + np.z);
            nx3 = __ldg(xrow + np.w);
            npw0 = __ldg(pat + 0 * NGROUPS + gn);
            npw1 = __ldg(pat + 1 * NGROUPS + gn);
            npw2 = __ldg(pat + 2 * NGROUPS + gn);
            npw3 = __ldg(pat + 3 * NGROUPS + gn);
            npw4 = __ldg(pat + 4 * NGROUPS + gn);
        }

        // activations
        float sg0, sg1, sg2, sg3, sp;
        {
            float ax, e, inv;
            ax = fabsf(x0); e = __expf(-ax); inv = __fdividef(1.f, 1.f + e);
            sg0 = (x0 >= 0.f) ? inv : e * inv;
            sp  = fmaxf(x0, 0.f) + __logf(1.f + e);
            ax = fabsf(x1); e = __expf(-ax); inv = __fdividef(1.f, 1.f + e);
            sg1 = (x1 >= 0.f) ? inv : e * inv;
            sp += fmaxf(x1, 0.f) + __logf(1.f + e);
            ax = fabsf(x2); e = __expf(-ax); inv = __fdividef(1.f, 1.f + e);
            sg2 = (x2 >= 0.f) ? inv : e * inv;
            sp += fmaxf(x2, 0.f) + __logf(1.f + e);
            ax = fabsf(x3); e = __expf(-ax); inv = __fdividef(1.f, 1.f + e);
            sg3 = (x3 >= 0.f) ? inv : e * inv;
            sp += fmaxf(x3, 0.f) + __logf(1.f + e);
        }
        spsum += sp;
        sgsum += sg0 + sg1 + sg2 + sg3;

        // 16 subset sums of the 4 packed (x, sg) values (11 FADD2)
        {
            ull p0 = f2pack(x0, sg0), p1 = f2pack(x1, sg1);
            ull p2 = f2pack(x2, sg2), p3 = f2pack(x3, sg3);
            ull s3  = add2(p0, p1);
            ull s5  = add2(p2, p0), s6 = add2(p2, p1), s7 = add2(p2, s3);
            ull s9  = add2(p3, p0), s10 = add2(p3, p1), s11 = add2(p3, s3);
            ull s12 = add2(p3, p2), s13 = add2(p3, s5), s14 = add2(p3, s6);
            ull s15 = add2(p3, s7);
            lut[0 * NT + tid]  = 0ull;
            lut[1 * NT + tid]  = p0;  lut[2 * NT + tid]  = p1;
            lut[3 * NT + tid]  = s3;  lut[4 * NT + tid]  = p2;
            lut[5 * NT + tid]  = s5;  lut[6 * NT + tid]  = s6;
            lut[7 * NT + tid]  = s7;  lut[8 * NT + tid]  = p3;
            lut[9 * NT + tid]  = s9;  lut[10 * NT + tid] = s10;
            lut[11 * NT + tid] = s11; lut[12 * NT + tid] = s12;
            lut[13 * NT + tid] = s13; lut[14 * NT + tid] = s14;
            lut[15 * NT + tid] = s15;
        }
        // per-thread LUT: same-thread read-after-write, no barrier needed

#pragma unroll
        for (int w = 0; w < 5; w++) {
            unsigned word = pw[w];
#pragma unroll
            for (int k = 0; k < 8; k++) {
                unsigned nib = (word >> (4 * k)) & 0xFu;
                ull v = lut[(nib << 8) + (unsigned)tid];
                acc[8 * w + k] = add2(acc[8 * w + k], v);
            }
        }
    }

    // ---- CTA reduction ----
    __shared__ float sx[M_HALF];
    __shared__ float ss[M_HALF];
    __shared__ float s_sp, s_sg;
    if (tid < M_HALF) { sx[tid] = 0.0f; ss[tid] = 0.0f; }
    if (tid == 0)     { s_sp = 0.0f; s_sg = 0.0f; }
    __syncthreads();

#pragma unroll
    for (int m = 0; m < M_HALF; m++) {
        float vx = __uint_as_float((unsigned)(acc[m] & 0xffffffffull));
        float vs = __uint_as_float((unsigned)(acc[m] >> 32));
#pragma unroll
        for (int off = 16; off > 0; off >>= 1) {
            vx += __shfl_xor_sync(0xffffffffu, vx, off);
            vs += __shfl_xor_sync(0xffffffffu, vs, off);
        }
        if (lane == 0) {
            atomicAdd(&sx[m], vx);
            atomicAdd(&ss[m], vs);
        }
    }
    {
        float vp = spsum, vg = sgsum;
#pragma unroll
        for (int off = 16; off > 0; off >>= 1) {
            vp += __shfl_xor_sync(0xffffffffu, vp, off);
            vg += __shfl_xor_sync(0xffffffffu, vg, off);
        }
        if (lane == 0) {
            atomicAdd(&s_sp, vp);
            atomicAdd(&s_sg, vg);
        }
    }
    __syncthreads();

    // ---- epilogue: softmax over K=134, assemble costs for this half ----
    __shared__ float lg[K_CLS];
    __shared__ float red[2];
    if (tid < K_CLS) lg[tid] = pred_logits[(size_t)n * K_CLS + tid];
    __syncthreads();
    if (tid == 0) {
        float mx = -1e30f;
        for (int k = 0; k < K_CLS; k++) mx = fmaxf(mx, lg[k]);
        float sm = 0.0f;
        for (int k = 0; k < K_CLS; k++) sm += __expf(lg[k] - mx);
        red[0] = mx;
        red[1] = __fdividef(1.0f, sm);
    }
    __syncthreads();
    if (tid < K_CLS) lg[tid] = __expf(lg[tid] - red[0]) * red[1];
    __syncthreads();

    if (tid < M_HALF) {
        const int mg = 40 * h + tid;
        float ysum = (float)g_ysum_i[mg];

        int lbl = tgt_labels[mg];
        lbl = min(max(lbl, 0), K_CLS - 1);
        float p  = lg[lbl];
        float xy = sx[tid];
        float sy = ss[tid];
        const float invPn = 1.0f / (float)PN;
        float cost_class = -p;
        float cost_mask  = (s_sp - xy) * invPn;
        float cost_dice  = 1.0f - (2.0f * sy + 1.0f) / (s_sg + ysum + 1.0f);
        out[(size_t)n * M_TGT + mg] =
            2.0f * cost_class + 5.0f * cost_mask + 5.0f * cost_dice;
    }
}

// ---------------------------------------------------------------------------
// Inputs (metadata order):
//   d_in[0] pred_logits f32 (4,100,134)
//   d_in[1] pred_masks  f32 (4,100,256,256)
//   d_in[2] tgt_labels  i32 (80)
//   d_in[3] tgt_masks   f32 (80,256,256)
//   d_in[4] point_idx   i32 (12544)
// out: f32 (4,100,80)
// ---------------------------------------------------------------------------
extern "C" void kernel_launch(void* const* d_in, const int* in_sizes, int n_in,
                              void* d_out, int out_size) {
    const float* pred_logits = (const float*)d_in[0];
    const float* pred_masks  = (const float*)d_in[1];
    const int*   tgt_labels  = (const int*)  d_in[2];
    const float* tgt_masks   = (const float*)d_in[3];
    const int*   point_idx   = (const int*)  d_in[4];
    float* out = (float*)d_out;

    hm_zero_kernel<<<1, 128>>>();
    hm_prep_kernel<<<PN / 32, 32>>>(tgt_masks, point_idx);
    hm_main_kernel<<<2 * N_ROWS, NT>>>(pred_logits, pred_masks, tgt_labels,
                                       point_idx, out);
}

// round 5
// speedup vs baseline: 1.5454x; 1.5454x over previous
#include <cuda_runtime.h>
#include <cuda_bf16.h>

// Fixed problem shapes
#define P_FULL   65536          // H*W
#define PN       12544          // sampled points
#define M_TGT    80             // targets
#define K_CLS    134            // classes
#define N_ROWS   400            // bs*Q
#define A_ROWS   800            // 2 per n: x row, sigmoid row
#define A_ROWS_P 896            // padded to 7*128
#define KCHUNK   256
#define NKC      (PN / KCHUNK)  // 49
#define MTILES   (A_ROWS_P / 128) // 7
#define JC       49             // j-chunks of 256 for prep_Y

typedef unsigned int u32;

// ---- static scratch (zero-init BSS; rows >=800 of g_A never written => stay 0)
__device__ __nv_bfloat16 g_A[(size_t)A_ROWS_P * PN];     // 22.5MB
__device__ __nv_bfloat16 g_Y[(size_t)M_TGT * PN];        // 2MB
__device__ float g_Dpart[(size_t)NKC * A_ROWS_P * M_TGT];// 14MB
__device__ float g_spsum[2 * N_ROWS];                    // [n*2+h]
__device__ float g_sgsum[2 * N_ROWS];
__device__ int   g_ycnt[M_TGT * JC];                     // per-(m,chunk) popcounts

// ---------------------------------------------------------------------------
// K1: build Y bf16 + ysum partial counts.
// grid (JC, M_TGT) x 256 threads; block (c, m) handles points [c*256, c*256+256)
// ---------------------------------------------------------------------------
__global__ void hm_prepY_kernel(const float* __restrict__ tgt_masks,
                                const int*   __restrict__ point_idx) {
    const int c = blockIdx.x, m = blockIdx.y;
    const int t = threadIdx.x;
    const int j = c * 256 + t;
    const int pj = __ldg(point_idx + j);
    float v = __ldg(tgt_masks + (size_t)m * P_FULL + pj);
    int on = (v != 0.0f);
    g_Y[(size_t)m * PN + j] = __float2bfloat16_rn(on ? 1.0f : 0.0f);

    unsigned ball = __ballot_sync(0xffffffffu, on);
    __shared__ int wc[8];
    if ((t & 31) == 0) wc[t >> 5] = __popc(ball);
    __syncthreads();
    if (t == 0) {
        int s = 0;
#pragma unroll
        for (int w = 0; w < 8; w++) s += wc[w];
        g_ycnt[m * JC + c] = s;
    }
}

// ---------------------------------------------------------------------------
// K2: build A rows (x, sigmoid) bf16 + per-half spsum/sgsum partials.
// grid 800 = (n, half) x 256 threads; half h covers j in [h*6272, h*6272+6272)
// ---------------------------------------------------------------------------
__global__ void __launch_bounds__(256)
hm_buildA_kernel(const float* __restrict__ pred_masks,
                 const int*   __restrict__ point_idx) {
    const int n = blockIdx.x >> 1;
    const int h = blockIdx.x & 1;
    const int t = threadIdx.x;
    const float* __restrict__ xrow = pred_masks + (size_t)n * P_FULL;
    const int jbase = h * (PN / 2);
    __nv_bfloat16* __restrict__ ax = g_A + (size_t)(2 * n) * PN;
    __nv_bfloat16* __restrict__ as = g_A + (size_t)(2 * n + 1) * PN;

    float spsum = 0.0f, sgsum = 0.0f;

    // 6272 points per block = 24.5 iterations of 256
#pragma unroll 4
    for (int i = 0; i < 24; i++) {
        int j = jbase + i * 256 + t;
        int pj = __ldg(point_idx + j);
        float x = __ldg(xrow + pj);
        float axv = fabsf(x);
        float e   = __expf(-axv);
        float inv = __fdividef(1.0f, 1.0f + e);
        float sg  = (x >= 0.0f) ? inv : e * inv;
        float sp  = fmaxf(x, 0.0f) + __logf(1.0f + e);
        spsum += sp; sgsum += sg;
        ax[j] = __float2bfloat16_rn(x);
        as[j] = __float2bfloat16_rn(sg);
    }
    if (t < 128) {
        int j = jbase + 24 * 256 + t;
        int pj = __ldg(point_idx + j);
        float x = __ldg(xrow + pj);
        float axv = fabsf(x);
        float e   = __expf(-axv);
        float inv = __fdividef(1.0f, 1.0f + e);
        float sg  = (x >= 0.0f) ? inv : e * inv;
        float sp  = fmaxf(x, 0.0f) + __logf(1.0f + e);
        spsum += sp; sgsum += sg;
        ax[j] = __float2bfloat16_rn(x);
        as[j] = __float2bfloat16_rn(sg);
    }

    // block reduce
    __shared__ float rp[8], rg[8];
#pragma unroll
    for (int off = 16; off > 0; off >>= 1) {
        spsum += __shfl_xor_sync(0xffffffffu, spsum, off);
        sgsum += __shfl_xor_sync(0xffffffffu, sgsum, off);
    }
    if ((t & 31) == 0) { rp[t >> 5] = spsum; rg[t >> 5] = sgsum; }
    __syncthreads();
    if (t == 0) {
        float sp = 0.0f, sg = 0.0f;
#pragma unroll
        for (int w = 0; w < 8; w++) { sp += rp[w]; sg += rg[w]; }
        g_spsum[n * 2 + h] = sp;
        g_sgsum[n * 2 + h] = sg;
    }
}

// ---------------------------------------------------------------------------
// K3: split-K bf16 GEMM via mma.sync m16n8k16.
// grid (MTILES, NKC) x 256 threads (8 warps). CTA tile 128(M) x 80(N) x 256(K).
// Warp w handles m-rows [w*16, w*16+16), all 10 n8 tiles.
// Smem pitch 264 bf16 (132 u32; 132%32=4 -> conflict-free frag loads).
// ---------------------------------------------------------------------------
#define SPITCH 132                    // u32 pitch
#define SMEM_A_U32 (128 * SPITCH)     // 16896 u32 = 67584 B
#define SMEM_B_U32 (80 * SPITCH)      // 10560 u32 = 42240 B
#define SMEM_K3_BYTES ((SMEM_A_U32 + SMEM_B_U32) * 4)

__global__ void __launch_bounds__(256)
hm_gemm_kernel() {
    extern __shared__ u32 sh[];
    u32* As = sh;                  // [128][132] u32
    u32* Bs = sh + SMEM_A_U32;     // [80][132]  u32

    const int bm = blockIdx.x;     // m-tile
    const int kc = blockIdx.y;     // k-chunk
    const int t  = threadIdx.x;
    const int warpid = t >> 5;
    const int lane = t & 31;
    const int g    = lane >> 2;
    const int tid4 = lane & 3;

    const u32* __restrict__ A32 = (const u32*)g_A;
    const u32* __restrict__ Y32 = (const u32*)g_Y;
    const int R = bm * 128;
    const int kw = kc * 128;       // u32 col offset of this k-chunk

    // cooperative fill: A tile 128 rows x 128 u32
#pragma unroll
    for (int i = 0; i < 64; i++) {
        int lin = t + 256 * i;     // 0..16383
        int r = lin >> 7, cu = lin & 127;
        As[r * SPITCH + cu] = A32[(size_t)(R + r) * (PN / 2) + kw + cu];
    }
    // B tile 80 rows x 128 u32
#pragma unroll
    for (int i = 0; i < 40; i++) {
        int lin = t + 256 * i;     // 0..10239
        int r = lin >> 7, cu = lin & 127;
        Bs[r * SPITCH + cu] = Y32[(size_t)r * (PN / 2) + kw + cu];
    }
    __syncthreads();

    float d[10][4];
#pragma unroll
    for (int nt = 0; nt < 10; nt++)
#pragma unroll
        for (int q = 0; q < 4; q++) d[nt][q] = 0.0f;

    const int wrow = warpid * 16;

#pragma unroll
    for (int ks = 0; ks < 16; ks++) {
        const int kcol = ks * 8;   // u32 col within chunk
        u32 a0, a1, a2, a3;
        {
            const u32* p = As + (wrow + g) * SPITCH + kcol + tid4;
            a0 = p[0];
            a1 = p[8 * SPITCH];
            a2 = p[4];
            a3 = p[8 * SPITCH + 4];
        }
#pragma unroll
        for (int nt = 0; nt < 10; nt++) {
            const u32* p = Bs + (nt * 8 + g) * SPITCH + kcol + tid4;
            u32 b0 = p[0];
            u32 b1 = p[4];
            asm volatile(
                "mma.sync.aligned.m16n8k16.row.col.f32.bf16.bf16.f32 "
                "{%0,%1,%2,%3}, {%4,%5,%6,%7}, {%8,%9}, {%0,%1,%2,%3};"
                : "+f"(d[nt][0]), "+f"(d[nt][1]), "+f"(d[nt][2]), "+f"(d[nt][3])
                : "r"(a0), "r"(a1), "r"(a2), "r"(a3), "r"(b0), "r"(b1));
        }
    }

    // store partials: D_part[kc][row][n]
    float* __restrict__ Dp = g_Dpart + (size_t)kc * A_ROWS_P * M_TGT;
    const int row0 = R + wrow + g;
#pragma unroll
    for (int nt = 0; nt < 10; nt++) {
        int ncol = nt * 8 + tid4 * 2;
        Dp[(size_t)row0 * M_TGT + ncol]           = d[nt][0];
        Dp[(size_t)row0 * M_TGT + ncol + 1]       = d[nt][1];
        Dp[(size_t)(row0 + 8) * M_TGT + ncol]     = d[nt][2];
        Dp[(size_t)(row0 + 8) * M_TGT + ncol + 1] = d[nt][3];
    }
}

// ---------------------------------------------------------------------------
// K4: reduce partials + softmax + cost assembly. grid 400 x 256 threads.
// ---------------------------------------------------------------------------
__global__ void __launch_bounds__(256)
hm_final_kernel(const float* __restrict__ pred_logits,
                const int*   __restrict__ tgt_labels,
                float*       __restrict__ out) {
    const int n = blockIdx.x;
    const int t = threadIdx.x;

    __shared__ float lg[K_CLS];
    __shared__ float rr[128];
    __shared__ float s_mx, s_inv;

    if (t < K_CLS) lg[t] = __ldg(pred_logits + (size_t)n * K_CLS + t);
    __syncthreads();

    // parallel max over 134 (fold into 128)
    if (t < 128) {
        float v = lg[t];
        if (t < K_CLS - 128) v = fmaxf(v, lg[t + 128]);
        rr[t] = v;
    }
    __syncthreads();
#pragma unroll
    for (int s = 64; s > 0; s >>= 1) {
        if (t < s) rr[t] = fmaxf(rr[t], rr[t + s]);
        __syncthreads();
    }
    if (t == 0) s_mx = rr[0];
    __syncthreads();
    // parallel sum of exp
    if (t < 128) {
        float v = __expf(lg[t] - s_mx);
        if (t < K_CLS - 128) v += __expf(lg[t + 128] - s_mx);
        rr[t] = v;
    }
    __syncthreads();
#pragma unroll
    for (int s = 64; s > 0; s >>= 1) {
        if (t < s) rr[t] += rr[t + s];
        __syncthreads();
    }
    if (t == 0) s_inv = __fdividef(1.0f, rr[0]);
    __syncthreads();

    if (t < M_TGT) {
        // xy, sy from 49 partials each
        const float* __restrict__ px = g_Dpart + (size_t)(2 * n) * M_TGT + t;
        const float* __restrict__ ps = g_Dpart + (size_t)(2 * n + 1) * M_TGT + t;
        float xy = 0.0f, sy = 0.0f;
#pragma unroll
        for (int kc = 0; kc < NKC; kc++) {
            xy += __ldg(px + (size_t)kc * A_ROWS_P * M_TGT);
            sy += __ldg(ps + (size_t)kc * A_ROWS_P * M_TGT);
        }
        int yc = 0;
#pragma unroll
        for (int c = 0; c < JC; c++) yc += __ldg(g_ycnt + t * JC + c);

        float sp = g_spsum[2 * n] + g_spsum[2 * n + 1];
        float sg = g_sgsum[2 * n] + g_sgsum[2 * n + 1];

        int lbl = __ldg(tgt_labels + t);
        lbl = min(max(lbl, 0), K_CLS - 1);
        float p = __expf(lg[lbl] - s_mx) * s_inv;

        const float invPn = 1.0f / (float)PN;
        float cost_class = -p;
        float cost_mask  = (sp - xy) * invPn;
        float cost_dice  = 1.0f - (2.0f * sy + 1.0f) / (sg + (float)yc + 1.0f);
        out[(size_t)n * M_TGT + t] =
            2.0f * cost_class + 5.0f * cost_mask + 5.0f * cost_dice;
    }
}

// ---------------------------------------------------------------------------
// Inputs (metadata order):
//   d_in[0] pred_logits f32 (4,100,134)
//   d_in[1] pred_masks  f32 (4,100,256,256)
//   d_in[2] tgt_labels  i32 (80)
//   d_in[3] tgt_masks   f32 (80,256,256)
//   d_in[4] point_idx   i32 (12544)
// out: f32 (4,100,80)
// ---------------------------------------------------------------------------
extern "C" void kernel_launch(void* const* d_in, const int* in_sizes, int n_in,
                              void* d_out, int out_size) {
    const float* pred_logits = (const float*)d_in[0];
    const float* pred_masks  = (const float*)d_in[1];
    const int*   tgt_labels  = (const int*)  d_in[2];
    const float* tgt_masks   = (const float*)d_in[3];
    const int*   point_idx   = (const int*)  d_in[4];
    float* out = (float*)d_out;

    static int smem_set = 0;
    if (!smem_set) {
        cudaFuncSetAttribute(hm_gemm_kernel,
                             cudaFuncAttributeMaxDynamicSharedMemorySize,
                             SMEM_K3_BYTES);
        smem_set = 1;
    }

    dim3 gy(JC, M_TGT);
    hm_prepY_kernel<<<gy, 256>>>(tgt_masks, point_idx);
    hm_buildA_kernel<<<2 * N_ROWS, 256>>>(pred_masks, point_idx);
    dim3 gg(MTILES, NKC);
    hm_gemm_kernel<<<gg, 256, SMEM_K3_BYTES>>>();
    hm_final_kernel<<<N_ROWS, 256>>>(pred_logits, tgt_labels, out);
}